// round 8
// baseline (speedup 1.0000x reference)
#include <cuda_runtime.h>

#define D_DIM    256
#define BM       128
#define BN       64
#define BK       64
#define NTHREADS 256
#define K_CENT   1024
#define N_MAX    131072

__device__ float g_cnorm[K_CENT];
__device__ float g_xnorm[N_MAX];

// Row sum-of-squares replicating XLA GPU row-reduction order for a 256-wide
// fp32 row: vec2 partials (128 threads), intra-warp shfl_down tree
// (16,8,4,2,1), cross-warp combine (s0+s2)+(s1+s3).
// All ops via __fmul_rn/__fadd_rn to forbid reassociation.
__device__ __forceinline__ float rownorm256(const float* __restrict__ row_ptr,
                                            int t, float* s4)
{
    float2 v = ((const float2*)row_ptr)[t];
    float p = __fmul_rn(v.x, v.x);
    p = __fadd_rn(p, __fmul_rn(v.y, v.y));
#pragma unroll
    for (int off = 16; off; off >>= 1)
        p = __fadd_rn(p, __shfl_down_sync(0xffffffffu, p, off));
    if ((t & 31) == 0) s4[t >> 5] = p;
    __syncthreads();
    return __fadd_rn(__fadd_rn(s4[0], s4[2]), __fadd_rn(s4[1], s4[3]));
}

__global__ void xnorm_kernel(const float* __restrict__ x) {
    __shared__ float s4[4];
    const int t = threadIdx.x;
    const long long row = blockIdx.x;
    float r = rownorm256(x + row * D_DIM, t, s4);
    if (t == 0) g_xnorm[row] = r;
}

__global__ void cnorm_kernel(const float* __restrict__ c) {
    __shared__ float s4[4];
    const int t = threadIdx.x;
    const long long row = blockIdx.x;
    float r = rownorm256(c + row * D_DIM, t, s4);
    if (t == 0) g_cnorm[row] = r;
}

// Fused GEMM + argmin + gather.
// score = fl( fl( (-2*dot) + xn ) + cn )  -- replication of the reference
// expression; dot is a single-accumulator ascending-k fma chain.
__global__ void __launch_bounds__(NTHREADS, 2)
vq_main_kernel(const float* __restrict__ x, const float* __restrict__ c,
               float* __restrict__ out, int N, int K)
{
    extern __shared__ float sm[];
    float* xs = sm;               // [BK][BM] k-major transposed, 32 KB
    float* cs = sm + BK * BM;     // [BK][BN] k-major transposed, 16 KB
    float* rv = cs;               // post-loop reuse: [BM][16] best values
    int*   ri = (int*)(cs + BM * 16);  // [BM][16] best indices

    const int tid = threadIdx.x;
    const int tx  = tid & 15;     // 0..15 -> 4 columns each
    const int ty  = tid >> 4;     // 0..15 -> 8 rows each
    const long long m0 = (long long)blockIdx.x * BM;

    // per-row |x|^2 (XLA-order, precomputed) for this thread's 8 rows
    float xn[8];
#pragma unroll
    for (int i = 0; i < 8; ++i) xn[i] = g_xnorm[m0 + ty * 8 + i];

    float bestv[8];
    int   besti[8];
#pragma unroll
    for (int i = 0; i < 8; ++i) { bestv[i] = 3.4e38f; besti[i] = 0; }

    for (int n0 = 0; n0 < K; n0 += BN) {
        float acc[8][4];
#pragma unroll
        for (int i = 0; i < 8; ++i)
#pragma unroll
            for (int j = 0; j < 4; ++j) acc[i][j] = 0.f;

        for (int k0 = 0; k0 < D_DIM; k0 += BK) {
            __syncthreads();   // previous chunk's compute reads are done
            // stage xs: x[m0+m][k0+kk] -> xs[kk][m]
#pragma unroll
            for (int it = 0; it < 8; ++it) {
                int idx = tid + it * NTHREADS;
                int m = idx >> 4, f4 = idx & 15;
                float4 v = ((const float4*)(x + (m0 + m) * D_DIM + k0))[f4];
                int kk = f4 * 4;
                xs[(kk + 0) * BM + m] = v.x;
                xs[(kk + 1) * BM + m] = v.y;
                xs[(kk + 2) * BM + m] = v.z;
                xs[(kk + 3) * BM + m] = v.w;
            }
            // stage cs: c[n0+n][k0+kk] -> cs[kk][n]
#pragma unroll
            for (int it = 0; it < 4; ++it) {
                int idx = tid + it * NTHREADS;
                int n = idx >> 4, f4 = idx & 15;
                float4 v = ((const float4*)(c + (long long)(n0 + n) * D_DIM + k0))[f4];
                int kk = f4 * 4;
                cs[(kk + 0) * BN + n] = v.x;
                cs[(kk + 1) * BN + n] = v.y;
                cs[(kk + 2) * BN + n] = v.z;
                cs[(kk + 3) * BN + n] = v.w;
            }
            __syncthreads();

            // ascending-k fma chain, single accumulator per output element
#pragma unroll 4
            for (int k = 0; k < BK; ++k) {
                float4 b  = *(const float4*)(cs + k * BN + tx * 4);
                float4 a0 = *(const float4*)(xs + k * BM + ty * 8);
                float4 a1 = *(const float4*)(xs + k * BM + ty * 8 + 4);
                float av[8] = {a0.x, a0.y, a0.z, a0.w, a1.x, a1.y, a1.z, a1.w};
                float bv[4] = {b.x, b.y, b.z, b.w};
#pragma unroll
                for (int i = 0; i < 8; ++i)
#pragma unroll
                    for (int j = 0; j < 4; ++j)
                        acc[i][j] = __fmaf_rn(av[i], bv[j], acc[i][j]);
            }
        }

        // reference-exact scoring + running argmin (first-index tie-break)
#pragma unroll
        for (int j = 0; j < 4; ++j) {
            int n = n0 + tx * 4 + j;
            float cn = g_cnorm[n];
#pragma unroll
            for (int i = 0; i < 8; ++i) {
                float t = __fadd_rn(__fmul_rn(-2.0f, acc[i][j]), xn[i]);
                float v = __fadd_rn(t, cn);
                if (v < bestv[i]) { bestv[i] = v; besti[i] = n; }
            }
        }
    }

    __syncthreads();   // all compute reads of cs finished; reuse as rv/ri

#pragma unroll
    for (int i = 0; i < 8; ++i) {
        int r = ty * 8 + i;
        rv[r * 16 + tx] = bestv[i];
        ri[r * 16 + tx] = besti[i];
    }
    __syncthreads();

    // cross-thread reduce per row with explicit lowest-index tie-break
    if (tid < BM) {
        float bv = rv[tid * 16];
        int   bi = ri[tid * 16];
#pragma unroll
        for (int t = 1; t < 16; ++t) {
            float v  = rv[tid * 16 + t];
            int   ix = ri[tid * 16 + t];
            if (v < bv || (v == bv && ix < bi)) { bv = v; bi = ix; }
        }
        ri[tid * 16] = bi;
    }
    __syncthreads();

    // gather centroids[best] -> out: 2 threads per row, 32 float4 each
    {
        int r    = tid >> 1;
        int half = tid & 1;
        int bi   = ri[r * 16];
        const float4* src = (const float4*)(c + (long long)bi * D_DIM) + half * 32;
        float4*       dst = (float4*)(out + (m0 + r) * D_DIM) + half * 32;
#pragma unroll
        for (int q = 0; q < 32; ++q) dst[q] = src[q];
    }
}

extern "C" void kernel_launch(void* const* d_in, const int* in_sizes, int n_in,
                              void* d_out, int out_size) {
    const float* x = (const float*)d_in[0];
    const float* c = (const float*)d_in[1];
    float* out = (float*)d_out;
    int N = in_sizes[0] / D_DIM;   // 131072
    int K = in_sizes[1] / D_DIM;   // 1024

    xnorm_kernel<<<N, 128>>>(x);
    cnorm_kernel<<<K, 128>>>(c);
    vq_main_kernel<<<N / BM, NTHREADS, (BK * BM + BK * BN) * sizeof(float)>>>(x, c, out, N, K);
}

// round 11
// speedup vs baseline: 2.7316x; 2.7316x over previous
#include <cuda_runtime.h>
#include <cuda_bf16.h>

#define D_DIM   256
#define K_CENT  1024
#define N_MAX   131072
#define MARGIN  0.75f

__device__ float          g_cnorm[K_CENT];
__device__ float          g_xnorm[N_MAX];
__device__ int            g_amb[N_MAX];
__device__ int            g_count;
__device__ __align__(16) __nv_bfloat16 g_xb[(size_t)N_MAX * D_DIM];  // 64 MB
__device__ __align__(16) __nv_bfloat16 g_cb[K_CENT * D_DIM];         // 512 KB

__global__ void zero_kernel() { if (threadIdx.x == 0) g_count = 0; }

// 4 rows per 512-thread block. Bit-exact R8 norm order (vec2 partials,
// shfl_down 16..1, (s0+s2)+(s1+s3)); also converts the row to bf16.
__global__ void normconv_kernel(const float* __restrict__ a, int mode) {
    __shared__ float s4[4][4];
    const int t  = threadIdx.x & 127;
    const int rs = threadIdx.x >> 7;
    const long long row = (long long)blockIdx.x * 4 + rs;
    float2 v = ((const float2*)(a + row * D_DIM))[t];
    __nv_bfloat162 bv = __floats2bfloat162_rn(v.x, v.y);
    if (mode == 0) ((__nv_bfloat162*)g_xb)[row * 128 + t] = bv;
    else           ((__nv_bfloat162*)g_cb)[row * 128 + t] = bv;
    float p = __fmul_rn(v.x, v.x);
    p = __fadd_rn(p, __fmul_rn(v.y, v.y));
#pragma unroll
    for (int off = 16; off; off >>= 1)
        p = __fadd_rn(p, __shfl_down_sync(0xffffffffu, p, off));
    if ((t & 31) == 0) s4[rs][t >> 5] = p;
    __syncthreads();
    if (t == 0) {
        float r = __fadd_rn(__fadd_rn(s4[rs][0], s4[rs][2]),
                            __fadd_rn(s4[rs][1], s4[rs][3]));
        if (mode == 0) g_xnorm[row] = r; else g_cnorm[row] = r;
    }
}

__device__ __forceinline__ void top2_update(float& v1, float& v2, int& i1,
                                            float s, int n) {
    if (s < v1)      { v2 = v1; v1 = s; i1 = n; }
    else if (s < v2) { v2 = s; }
}

// Pass 1: bf16 mma.sync (m16n8k16) GEMM; approx score = -2*dot + cn.
// Per CTA: 128 x-rows x 1024 centroids. Top-2 + margin gate + fused gather.
__global__ void __launch_bounds__(256, 2)
vq_pass1(const float* __restrict__ c, float* __restrict__ out)
{
    extern __shared__ char smem[];
    __nv_bfloat16* xs  = (__nv_bfloat16*)smem;             // [128][72]
    __nv_bfloat16* cs  = (__nv_bfloat16*)(smem + 18432);   // [128][72]
    float*         cns = (float*)(smem + 36864);           // [1024]
    int*           si  = (int*)(smem + 40960);             // [128]

    const int tid  = threadIdx.x;
    const int lane = tid & 31, warp = tid >> 5;
    const int r0   = warp * 16 + (lane >> 2);   // rows r0, r0+8
    const int kp   = (lane & 3) * 2;
    const long long m0 = (long long)blockIdx.x * 128;

    for (int i = tid; i < K_CENT; i += 256) cns[i] = g_cnorm[i];

    float v1[2] = {3.4e38f, 3.4e38f}, v2[2] = {3.4e38f, 3.4e38f};
    int   i1[2] = {0, 0};

    for (int n0t = 0; n0t < 8; ++n0t) {
        const int n0 = n0t * 128;
        float acc[16][4];
#pragma unroll
        for (int s = 0; s < 16; ++s)
#pragma unroll
            for (int j = 0; j < 4; ++j) acc[s][j] = 0.f;

        for (int k0 = 0; k0 < D_DIM; k0 += 64) {
            __syncthreads();
            // stage xs: 128 rows x 64 bf16 = 1024 uint4 (4 iters of 256)
#pragma unroll
            for (int it = 0; it < 4; ++it) {
                int idx = it * 256 + tid;
                int m = idx >> 3, u = idx & 7;
                uint4 vv = ((const uint4*)(g_xb + (m0 + m) * D_DIM + k0))[u];
                *(uint4*)(xs + m * 72 + u * 8) = vv;
            }
            // stage cs: 128 rows x 64 bf16 = 1024 uint4 (4 iters of 256)
#pragma unroll
            for (int it = 0; it < 4; ++it) {
                int idx = it * 256 + tid;
                int n = idx >> 3, u = idx & 7;
                uint4 vv = ((const uint4*)(g_cb + (size_t)(n0 + n) * D_DIM + k0))[u];
                *(uint4*)(cs + n * 72 + u * 8) = vv;
            }
            __syncthreads();

#pragma unroll
            for (int kk = 0; kk < 64; kk += 16) {
                unsigned a0 = *(const unsigned*)(xs + r0 * 72 + kk + kp);
                unsigned a1 = *(const unsigned*)(xs + (r0 + 8) * 72 + kk + kp);
                unsigned a2 = *(const unsigned*)(xs + r0 * 72 + kk + kp + 8);
                unsigned a3 = *(const unsigned*)(xs + (r0 + 8) * 72 + kk + kp + 8);
#pragma unroll
                for (int s = 0; s < 16; ++s) {
                    int nb = s * 8 + (lane >> 2);
                    unsigned b0 = *(const unsigned*)(cs + nb * 72 + kk + kp);
                    unsigned b1 = *(const unsigned*)(cs + nb * 72 + kk + kp + 8);
                    asm volatile(
                        "mma.sync.aligned.m16n8k16.row.col.f32.bf16.bf16.f32 "
                        "{%0,%1,%2,%3}, {%4,%5,%6,%7}, {%8,%9}, {%0,%1,%2,%3};"
                        : "+f"(acc[s][0]), "+f"(acc[s][1]),
                          "+f"(acc[s][2]), "+f"(acc[s][3])
                        : "r"(a0), "r"(a1), "r"(a2), "r"(a3), "r"(b0), "r"(b1));
                }
            }
        }

        // epilogue: approx scores; n ascending per thread
#pragma unroll
        for (int s = 0; s < 16; ++s) {
            int n = n0 + s * 8 + kp;
            float cn0 = cns[n], cn1 = cns[n + 1];
            top2_update(v1[0], v2[0], i1[0], fmaf(-2.f, acc[s][0], cn0), n);
            top2_update(v1[0], v2[0], i1[0], fmaf(-2.f, acc[s][1], cn1), n + 1);
            top2_update(v1[1], v2[1], i1[1], fmaf(-2.f, acc[s][2], cn0), n);
            top2_update(v1[1], v2[1], i1[1], fmaf(-2.f, acc[s][3], cn1), n + 1);
        }
    }

    // quad reduce (lanes 4q..4q+3 share rows r0, r0+8)
#pragma unroll
    for (int off = 1; off <= 2; off <<= 1) {
#pragma unroll
        for (int rp = 0; rp < 2; ++rp) {
            float ov1 = __shfl_xor_sync(0xffffffffu, v1[rp], off);
            int   oi1 = __shfl_xor_sync(0xffffffffu, i1[rp], off);
            float ov2 = __shfl_xor_sync(0xffffffffu, v2[rp], off);
            if (ov1 < v1[rp] || (ov1 == v1[rp] && oi1 < i1[rp])) {
                v2[rp] = fminf(v1[rp], ov2);
                v1[rp] = ov1; i1[rp] = oi1;
            } else {
                v2[rp] = fminf(v2[rp], ov1);
            }
        }
    }
    if ((lane & 3) == 0) {
        si[r0]     = i1[0];
        si[r0 + 8] = i1[1];
        if (v2[0] - v1[0] < MARGIN) {
            int p = atomicAdd(&g_count, 1); g_amb[p] = (int)(m0 + r0);
        }
        if (v2[1] - v1[1] < MARGIN) {
            int p = atomicAdd(&g_count, 1); g_amb[p] = (int)(m0 + r0 + 8);
        }
    }
    __syncthreads();

    // fused gather (fp32 centroids): 2 threads per row
    {
        int rr = tid >> 1, half = tid & 1;
        int bi = si[rr];
        const float4* src = (const float4*)(c + (size_t)bi * D_DIM) + half * 32;
        float4*       dst = (float4*)(out + (m0 + rr) * D_DIM) + half * 32;
#pragma unroll
        for (int q = 0; q < 32; ++q) dst[q] = src[q];
    }
}

// Rescore ambiguous rows with the verbatim R8 exact chain
// (ascending-k single-accumulator FFMA; fl(fl(-2*dot+xn)+cn); first-index).
__global__ void __launch_bounds__(256)
vq_rescore(const float* __restrict__ x, const float* __restrict__ c,
           float* __restrict__ out)
{
    extern __shared__ float sm[];
    float* xs = sm;                    // [64][32] k-major
    float* cs = sm + 64 * 32;          // [64][64] k-major
    float* rv = cs;                    // reuse: [32][16]
    int*   ri = (int*)(cs + 32 * 16);  // reuse: [32][16]
    int*   rows = (int*)(sm + 64 * 32 + 64 * 64);   // [32]
    int*   fi   = rows + 32;                        // [32]

    const int tid = threadIdx.x;
    const int tx  = tid & 15;          // 4 cols each -> 64
    const int ty  = tid >> 4;          // 2 rows each -> 32
    const int count = g_count;
    const int ntiles = (count + 31) >> 5;

    for (int tile = blockIdx.x; tile < ntiles; tile += gridDim.x) {
        const int t0 = tile << 5;
        if (tid < 32) {
            int gi = t0 + tid; if (gi > count - 1) gi = count - 1;
            rows[tid] = g_amb[gi];
        }
        __syncthreads();

        float xn[2];
#pragma unroll
        for (int i = 0; i < 2; ++i) xn[i] = g_xnorm[rows[ty * 2 + i]];

        float bestv[2]; int besti[2];
#pragma unroll
        for (int i = 0; i < 2; ++i) { bestv[i] = 3.4e38f; besti[i] = 0; }

        for (int n0 = 0; n0 < K_CENT; n0 += 64) {
            float acc[2][4];
#pragma unroll
            for (int i = 0; i < 2; ++i)
#pragma unroll
                for (int j = 0; j < 4; ++j) acc[i][j] = 0.f;

            for (int k0 = 0; k0 < D_DIM; k0 += 64) {
                __syncthreads();
                // stage xs: 32 rows x 64 k (transposed): 512 float4
#pragma unroll
                for (int it = 0; it < 2; ++it) {
                    int idx = it * 256 + tid;
                    int m = idx >> 4, f4 = idx & 15;
                    float4 v = ((const float4*)(x + (size_t)rows[m] * D_DIM + k0))[f4];
                    int kk = f4 * 4;
                    xs[(kk + 0) * 32 + m] = v.x;
                    xs[(kk + 1) * 32 + m] = v.y;
                    xs[(kk + 2) * 32 + m] = v.z;
                    xs[(kk + 3) * 32 + m] = v.w;
                }
                // stage cs: 64 rows x 64 k (transposed): 1024 float4
#pragma unroll
                for (int it = 0; it < 4; ++it) {
                    int idx = it * 256 + tid;
                    int n = idx >> 4, f4 = idx & 15;
                    float4 v = ((const float4*)(c + (size_t)(n0 + n) * D_DIM + k0))[f4];
                    int kk = f4 * 4;
                    cs[(kk + 0) * 64 + n] = v.x;
                    cs[(kk + 1) * 64 + n] = v.y;
                    cs[(kk + 2) * 64 + n] = v.z;
                    cs[(kk + 3) * 64 + n] = v.w;
                }
                __syncthreads();

#pragma unroll 4
                for (int k = 0; k < 64; ++k) {
                    float4 b = *(const float4*)(cs + k * 64 + tx * 4);
                    float a0 = xs[k * 32 + ty * 2];
                    float a1 = xs[k * 32 + ty * 2 + 1];
                    float bv4[4] = {b.x, b.y, b.z, b.w};
#pragma unroll
                    for (int j = 0; j < 4; ++j) {
                        acc[0][j] = __fmaf_rn(a0, bv4[j], acc[0][j]);
                        acc[1][j] = __fmaf_rn(a1, bv4[j], acc[1][j]);
                    }
                }
            }
#pragma unroll
            for (int j = 0; j < 4; ++j) {
                int n = n0 + tx * 4 + j;
                float cn = g_cnorm[n];
#pragma unroll
                for (int i = 0; i < 2; ++i) {
                    float t = __fadd_rn(__fmul_rn(-2.0f, acc[i][j]), xn[i]);
                    float v = __fadd_rn(t, cn);
                    if (v < bestv[i]) { bestv[i] = v; besti[i] = n; }
                }
            }
        }

        __syncthreads();   // xs/cs reads done; reuse as rv/ri
#pragma unroll
        for (int i = 0; i < 2; ++i) {
            int r = ty * 2 + i;
            rv[r * 16 + tx] = bestv[i];
            ri[r * 16 + tx] = besti[i];
        }
        __syncthreads();

        if (tid < 32) {
            float bv = rv[tid * 16];
            int   bi = ri[tid * 16];
#pragma unroll
            for (int t = 1; t < 16; ++t) {
                float v  = rv[tid * 16 + t];
                int   ix = ri[tid * 16 + t];
                if (v < bv || (v == bv && ix < bi)) { bv = v; bi = ix; }
            }
            fi[tid] = bi;
        }
        __syncthreads();

        // write out: 8 threads per row, 8 float4 each
        {
            int r = tid >> 3, q0 = (tid & 7) * 8;
            size_t rowid = (size_t)rows[r];
            int bi = fi[r];
            const float4* src = (const float4*)(c + (size_t)bi * D_DIM) + q0;
            float4*       dst = (float4*)(out + rowid * D_DIM) + q0;
#pragma unroll
            for (int q = 0; q < 8; ++q) dst[q] = src[q];
        }
        __syncthreads();
    }
}

extern "C" void kernel_launch(void* const* d_in, const int* in_sizes, int n_in,
                              void* d_out, int out_size) {
    const float* x = (const float*)d_in[0];
    const float* c = (const float*)d_in[1];
    float* out = (float*)d_out;
    int N = in_sizes[0] / D_DIM;   // 131072
    int K = in_sizes[1] / D_DIM;   // 1024

    zero_kernel<<<1, 32>>>();
    normconv_kernel<<<N / 4, 512>>>(x, 0);
    normconv_kernel<<<K / 4, 512>>>(c, 1);
    vq_pass1<<<N / 128, 256, 41472>>>(c, out);
    vq_rescore<<<256, 256, (64 * 32 + 64 * 64) * sizeof(float) + 256>>>(x, c, out);
}

// round 12
// speedup vs baseline: 3.2032x; 1.1726x over previous
#include <cuda_runtime.h>
#include <cuda_bf16.h>

#define D_DIM   256
#define K_CENT  1024
#define N_MAX   131072
#define MARGIN  2e-3f

__device__ float g_cnorm[K_CENT];
__device__ int   g_amb[N_MAX];
__device__ int   g_count;

__global__ void zero_kernel() { if (threadIdx.x == 0) g_count = 0; }

// XLA-order row sum-of-squares (vec2 partials, shfl_down 16..1,
// cross-warp (s0+s2)+(s1+s3)); bit-exact R8 chain. 4 rows / 512-thr block.
__global__ void cnorm_kernel(const float* __restrict__ c) {
    __shared__ float s4[4][4];
    const int t  = threadIdx.x & 127;
    const int rs = threadIdx.x >> 7;
    const int row = blockIdx.x * 4 + rs;
    float2 v = ((const float2*)(c + (size_t)row * D_DIM))[t];
    float p = __fmul_rn(v.x, v.x);
    p = __fadd_rn(p, __fmul_rn(v.y, v.y));
#pragma unroll
    for (int off = 16; off; off >>= 1)
        p = __fadd_rn(p, __shfl_down_sync(0xffffffffu, p, off));
    if ((t & 31) == 0) s4[rs][t >> 5] = p;
    __syncthreads();
    if (t == 0)
        g_cnorm[row] = __fadd_rn(__fadd_rn(s4[rs][0], s4[rs][2]),
                                 __fadd_rn(s4[rs][1], s4[rs][3]));
}

__device__ __forceinline__ void top2_update(float& v1, float& v2, int& i1,
                                            float s, int n) {
    if (s < v1)      { v2 = v1; v1 = s; i1 = n; }
    else if (s < v2) { v2 = s; }
}

#define LDSM_X4(R, addr) \
    asm volatile("ldmatrix.sync.aligned.m8n8.x4.shared.b16 {%0,%1,%2,%3}, [%4];" \
        : "=r"((R)[0]), "=r"((R)[1]), "=r"((R)[2]), "=r"((R)[3]) : "r"(addr))

#define MMA16816(A, B0, B1, C) \
    asm volatile("mma.sync.aligned.m16n8k16.row.col.f32.bf16.bf16.f32 " \
        "{%0,%1,%2,%3}, {%4,%5,%6,%7}, {%8,%9}, {%0,%1,%2,%3};" \
        : "+f"((C)[0]), "+f"((C)[1]), "+f"((C)[2]), "+f"((C)[3]) \
        : "r"((A)[0]), "r"((A)[1]), "r"((A)[2]), "r"((A)[3]), "r"(B0), "r"(B1))

// Pass 1: split-bf16 (hh+lh+hl) mma.sync GEMM; score = -2*dot + cn.
// CTA: 128 x-rows x 1024 centroids; warp tile m32 x n64; ldmatrix fragments.
// k-chunks of 32; smem bf16 arrays [128][40] (80B row stride).
__global__ void __launch_bounds__(256, 2)
vq_pass1(const float* __restrict__ x, const float* __restrict__ c,
         float* __restrict__ out)
{
    extern __shared__ char smem[];
    __nv_bfloat16* xs_hi = (__nv_bfloat16*)(smem);           // 10240 B
    __nv_bfloat16* cs_hi = (__nv_bfloat16*)(smem + 20480);   // 10240 B
    float* cns = (float*)(smem + 40960);                     // 1024 f32
    int*   si  = (int*)(smem + 45056);                       // 128 int
    // xs_lo at +10240 from xs_hi, cs_lo at +10240 from cs_hi
    // reduce arrays (post-mainloop) alias xs_hi:
    float* rv1 = (float*)(smem);            // [128][2]
    float* rv2 = (float*)(smem + 1024);     // [128][2]
    int*   ri1 = (int*)(smem + 2048);       // [128][2]

    const int tid  = threadIdx.x;
    const int lane = tid & 31, warp = tid >> 5;
    const int warp_m = warp & 3, warp_n = warp >> 2;
    const int wm0 = warp_m * 32, wn0 = warp_n * 64;
    const int lrow = lane >> 2, kp = (lane & 3) * 2;
    const long long m0 = (long long)blockIdx.x * 128;

    for (int i = tid; i < K_CENT; i += 256) cns[i] = g_cnorm[i];

    const unsigned xs_sh = (unsigned)__cvta_generic_to_shared(xs_hi);
    const unsigned cs_sh = (unsigned)__cvta_generic_to_shared(cs_hi);
    unsigned aAddr[2], bAddr[4];
#pragma unroll
    for (int mi = 0; mi < 2; ++mi)
        aAddr[mi] = xs_sh +
            ((wm0 + mi * 16 + (lane & 15)) * 40 + (lane >> 4) * 8) * 2;
#pragma unroll
    for (int q = 0; q < 4; ++q)
        bAddr[q] = cs_sh +
            ((wn0 + q * 16 + ((lane >> 4) & 1) * 8 + (lane & 7)) * 40 +
             ((lane >> 3) & 1) * 8) * 2;

    float v1[4], v2[4]; int i1[4];
#pragma unroll
    for (int r = 0; r < 4; ++r) { v1[r] = 3.4e38f; v2[r] = 3.4e38f; i1[r] = 0; }

    for (int n0t = 0; n0t < 8; ++n0t) {
        const int n0 = n0t * 128;
        float acc[2][8][4];
#pragma unroll
        for (int mi = 0; mi < 2; ++mi)
#pragma unroll
            for (int ni = 0; ni < 8; ++ni)
#pragma unroll
                for (int j = 0; j < 4; ++j) acc[mi][ni][j] = 0.f;

        for (int k0 = 0; k0 < D_DIM; k0 += 32) {
            __syncthreads();
            // stage xs hi/lo: 128 rows x 32 floats = 1024 float4 (4/thread)
#pragma unroll
            for (int it = 0; it < 4; ++it) {
                int idx = it * 256 + tid;
                int m = idx >> 3, u = idx & 7;
                float4 v = ((const float4*)(x + (m0 + m) * D_DIM + k0))[u];
                __nv_bfloat162 h01 = __floats2bfloat162_rn(v.x, v.y);
                __nv_bfloat162 h23 = __floats2bfloat162_rn(v.z, v.w);
                __nv_bfloat162 l01 = __floats2bfloat162_rn(
                    v.x - __bfloat162float(h01.x), v.y - __bfloat162float(h01.y));
                __nv_bfloat162 l23 = __floats2bfloat162_rn(
                    v.z - __bfloat162float(h23.x), v.w - __bfloat162float(h23.y));
                uint2 uh = make_uint2(*(unsigned*)&h01, *(unsigned*)&h23);
                uint2 ul = make_uint2(*(unsigned*)&l01, *(unsigned*)&l23);
                *(uint2*)((char*)xs_hi + m * 80 + u * 8)         = uh;
                *(uint2*)((char*)xs_hi + 10240 + m * 80 + u * 8) = ul;
            }
            // stage cs hi/lo: 128 c-rows x 32 floats
#pragma unroll
            for (int it = 0; it < 4; ++it) {
                int idx = it * 256 + tid;
                int n = idx >> 3, u = idx & 7;
                float4 v = ((const float4*)(c + (size_t)(n0 + n) * D_DIM + k0))[u];
                __nv_bfloat162 h01 = __floats2bfloat162_rn(v.x, v.y);
                __nv_bfloat162 h23 = __floats2bfloat162_rn(v.z, v.w);
                __nv_bfloat162 l01 = __floats2bfloat162_rn(
                    v.x - __bfloat162float(h01.x), v.y - __bfloat162float(h01.y));
                __nv_bfloat162 l23 = __floats2bfloat162_rn(
                    v.z - __bfloat162float(h23.x), v.w - __bfloat162float(h23.y));
                uint2 uh = make_uint2(*(unsigned*)&h01, *(unsigned*)&h23);
                uint2 ul = make_uint2(*(unsigned*)&l01, *(unsigned*)&l23);
                *(uint2*)((char*)cs_hi + n * 80 + u * 8)         = uh;
                *(uint2*)((char*)cs_hi + 10240 + n * 80 + u * 8) = ul;
            }
            __syncthreads();

#pragma unroll
            for (int kk = 0; kk < 32; kk += 16) {
                unsigned ah[2][4], al[2][4];
#pragma unroll
                for (int mi = 0; mi < 2; ++mi) {
                    LDSM_X4(ah[mi], aAddr[mi] + kk * 2);
                    LDSM_X4(al[mi], aAddr[mi] + 10240 + kk * 2);
                }
#pragma unroll
                for (int g = 0; g < 2; ++g) {
                    unsigned bh[2][4], bl[2][4];
#pragma unroll
                    for (int p = 0; p < 2; ++p) {
                        LDSM_X4(bh[p], bAddr[g * 2 + p] + kk * 2);
                        LDSM_X4(bl[p], bAddr[g * 2 + p] + 10240 + kk * 2);
                    }
#pragma unroll
                    for (int mi = 0; mi < 2; ++mi)
#pragma unroll
                        for (int p = 0; p < 2; ++p)
#pragma unroll
                            for (int h = 0; h < 2; ++h) {
                                int ni = g * 4 + p * 2 + h;
                                MMA16816(ah[mi], bh[p][2*h], bh[p][2*h+1], acc[mi][ni]);
                                MMA16816(al[mi], bh[p][2*h], bh[p][2*h+1], acc[mi][ni]);
                                MMA16816(ah[mi], bl[p][2*h], bl[p][2*h+1], acc[mi][ni]);
                            }
                }
            }
        }

        // epilogue: scores, n ascending per thread
#pragma unroll
        for (int ni = 0; ni < 8; ++ni) {
            int n = n0 + wn0 + ni * 8 + kp;
            float cn0 = cns[n], cn1 = cns[n + 1];
#pragma unroll
            for (int mi = 0; mi < 2; ++mi) {
                top2_update(v1[mi*2], v2[mi*2], i1[mi*2],
                            fmaf(-2.f, acc[mi][ni][0], cn0), n);
                top2_update(v1[mi*2], v2[mi*2], i1[mi*2],
                            fmaf(-2.f, acc[mi][ni][1], cn1), n + 1);
                top2_update(v1[mi*2+1], v2[mi*2+1], i1[mi*2+1],
                            fmaf(-2.f, acc[mi][ni][2], cn0), n);
                top2_update(v1[mi*2+1], v2[mi*2+1], i1[mi*2+1],
                            fmaf(-2.f, acc[mi][ni][3], cn1), n + 1);
            }
        }
    }

    // quad reduce (lanes 4q..4q+3 share the same 4 rows)
#pragma unroll
    for (int off = 1; off <= 2; off <<= 1) {
#pragma unroll
        for (int rp = 0; rp < 4; ++rp) {
            float ov1 = __shfl_xor_sync(0xffffffffu, v1[rp], off);
            int   oi1 = __shfl_xor_sync(0xffffffffu, i1[rp], off);
            float ov2 = __shfl_xor_sync(0xffffffffu, v2[rp], off);
            if (ov1 < v1[rp] || (ov1 == v1[rp] && oi1 < i1[rp])) {
                v2[rp] = fminf(v1[rp], ov2);
                v1[rp] = ov1; i1[rp] = oi1;
            } else {
                v2[rp] = fminf(v2[rp], ov1);
            }
        }
    }

    __syncthreads();   // all fragment reads done; alias xs_hi as rv/ri
    if ((lane & 3) == 0) {
#pragma unroll
        for (int rp = 0; rp < 4; ++rp) {
            int row = wm0 + (rp >> 1) * 16 + (rp & 1) * 8 + lrow;
            rv1[row * 2 + warp_n] = v1[rp];
            rv2[row * 2 + warp_n] = v2[rp];
            ri1[row * 2 + warp_n] = i1[rp];
        }
    }
    __syncthreads();

    if (tid < 128) {
        float a1 = rv1[tid * 2], a2 = rv2[tid * 2];
        int   ai = ri1[tid * 2];
        float b1 = rv1[tid * 2 + 1], b2 = rv2[tid * 2 + 1];
        int   bi = ri1[tid * 2 + 1];
        float fv1, fv2; int fi;
        if (a1 < b1 || (a1 == b1 && ai < bi)) {
            fv1 = a1; fi = ai; fv2 = fminf(a2, b1);
        } else {
            fv1 = b1; fi = bi; fv2 = fminf(b2, a1);
        }
        si[tid] = fi;
        if (fv2 - fv1 < MARGIN) {
            int p = atomicAdd(&g_count, 1);
            g_amb[p] = (int)(m0 + tid);
        }
    }
    __syncthreads();

    // fused gather (fp32 centroids): 2 threads per row
    {
        int rr = tid >> 1, half = tid & 1;
        int bi = si[rr];
        const float4* src = (const float4*)(c + (size_t)bi * D_DIM) + half * 32;
        float4*       dst = (float4*)(out + (m0 + rr) * D_DIM) + half * 32;
#pragma unroll
        for (int q = 0; q < 32; ++q) dst[q] = src[q];
    }
}

// Rescore ambiguous rows with the verbatim R8 exact chain; xn computed
// locally with the bit-exact XLA reduction order.
__global__ void __launch_bounds__(256)
vq_rescore(const float* __restrict__ x, const float* __restrict__ c,
           float* __restrict__ out)
{
    extern __shared__ float sm[];
    float* xs = sm;                    // [64][32] k-major
    float* cs = sm + 64 * 32;          // [64][64] k-major
    float* rv = cs;                    // reuse: [32][16]
    int*   ri = (int*)(cs + 32 * 16);  // reuse: [32][16]
    int*   rows = (int*)(sm + 6144);   // [32]
    int*   fi   = rows + 32;           // [32]
    float* xnv  = (float*)(fi + 32);   // [32]
    float* s4   = xnv + 32;            // [8]

    const int tid = threadIdx.x;
    const int tx  = tid & 15;
    const int ty  = tid >> 4;
    const int count = g_count;
    const int ntiles = (count + 31) >> 5;

    for (int tile = blockIdx.x; tile < ntiles; tile += gridDim.x) {
        const int t0 = tile << 5;
        if (tid < 32) {
            int gi = t0 + tid; if (gi > count - 1) gi = count - 1;
            rows[tid] = g_amb[gi];
        }
        __syncthreads();

        // xn for 32 rows, XLA order (two 128-thread groups, 16 iterations)
        {
            const int grp = tid >> 7;
            const int t = tid & 127;
            for (int it = 0; it < 16; ++it) {
                int r = it * 2 + grp;
                float2 v = ((const float2*)(x + (size_t)rows[r] * D_DIM))[t];
                float p = __fmul_rn(v.x, v.x);
                p = __fadd_rn(p, __fmul_rn(v.y, v.y));
#pragma unroll
                for (int off = 16; off; off >>= 1)
                    p = __fadd_rn(p, __shfl_down_sync(0xffffffffu, p, off));
                if ((t & 31) == 0) s4[grp * 4 + (t >> 5)] = p;
                __syncthreads();
                if (t == 0)
                    xnv[r] = __fadd_rn(
                        __fadd_rn(s4[grp * 4 + 0], s4[grp * 4 + 2]),
                        __fadd_rn(s4[grp * 4 + 1], s4[grp * 4 + 3]));
                __syncthreads();
            }
        }

        float xn[2];
#pragma unroll
        for (int i = 0; i < 2; ++i) xn[i] = xnv[ty * 2 + i];

        float bestv[2]; int besti[2];
#pragma unroll
        for (int i = 0; i < 2; ++i) { bestv[i] = 3.4e38f; besti[i] = 0; }

        for (int n0 = 0; n0 < K_CENT; n0 += 64) {
            float acc[2][4];
#pragma unroll
            for (int i = 0; i < 2; ++i)
#pragma unroll
                for (int j = 0; j < 4; ++j) acc[i][j] = 0.f;

            for (int k0 = 0; k0 < D_DIM; k0 += 64) {
                __syncthreads();
#pragma unroll
                for (int it = 0; it < 2; ++it) {
                    int idx = it * 256 + tid;
                    int m = idx >> 4, f4 = idx & 15;
                    float4 v = ((const float4*)(x + (size_t)rows[m] * D_DIM + k0))[f4];
                    int kk = f4 * 4;
                    xs[(kk + 0) * 32 + m] = v.x;
                    xs[(kk + 1) * 32 + m] = v.y;
                    xs[(kk + 2) * 32 + m] = v.z;
                    xs[(kk + 3) * 32 + m] = v.w;
                }
#pragma unroll
                for (int it = 0; it < 4; ++it) {
                    int idx = it * 256 + tid;
                    int n = idx >> 4, f4 = idx & 15;
                    float4 v = ((const float4*)(c + (size_t)(n0 + n) * D_DIM + k0))[f4];
                    int kk = f4 * 4;
                    cs[(kk + 0) * 64 + n] = v.x;
                    cs[(kk + 1) * 64 + n] = v.y;
                    cs[(kk + 2) * 64 + n] = v.z;
                    cs[(kk + 3) * 64 + n] = v.w;
                }
                __syncthreads();

#pragma unroll 4
                for (int k = 0; k < 64; ++k) {
                    float4 b = *(const float4*)(cs + k * 64 + tx * 4);
                    float a0 = xs[k * 32 + ty * 2];
                    float a1 = xs[k * 32 + ty * 2 + 1];
                    float bv4[4] = {b.x, b.y, b.z, b.w};
#pragma unroll
                    for (int j = 0; j < 4; ++j) {
                        acc[0][j] = __fmaf_rn(a0, bv4[j], acc[0][j]);
                        acc[1][j] = __fmaf_rn(a1, bv4[j], acc[1][j]);
                    }
                }
            }
#pragma unroll
            for (int j = 0; j < 4; ++j) {
                int n = n0 + tx * 4 + j;
                float cn = g_cnorm[n];
#pragma unroll
                for (int i = 0; i < 2; ++i) {
                    float t = __fadd_rn(__fmul_rn(-2.0f, acc[i][j]), xn[i]);
                    float v = __fadd_rn(t, cn);
                    if (v < bestv[i]) { bestv[i] = v; besti[i] = n; }
                }
            }
        }

        __syncthreads();
#pragma unroll
        for (int i = 0; i < 2; ++i) {
            int r = ty * 2 + i;
            rv[r * 16 + tx] = bestv[i];
            ri[r * 16 + tx] = besti[i];
        }
        __syncthreads();

        if (tid < 32) {
            float bv = rv[tid * 16];
            int   bi = ri[tid * 16];
#pragma unroll
            for (int t = 1; t < 16; ++t) {
                float v  = rv[tid * 16 + t];
                int   ix = ri[tid * 16 + t];
                if (v < bv || (v == bv && ix < bi)) { bv = v; bi = ix; }
            }
            fi[tid] = bi;
        }
        __syncthreads();

        {
            int r = tid >> 3, q0 = (tid & 7) * 8;
            size_t rowid = (size_t)rows[r];
            int bi = fi[r];
            const float4* src = (const float4*)(c + (size_t)bi * D_DIM) + q0;
            float4*       dst = (float4*)(out + rowid * D_DIM) + q0;
#pragma unroll
            for (int q = 0; q < 8; ++q) dst[q] = src[q];
        }
        __syncthreads();
    }
}

extern "C" void kernel_launch(void* const* d_in, const int* in_sizes, int n_in,
                              void* d_out, int out_size) {
    const float* x = (const float*)d_in[0];
    const float* c = (const float*)d_in[1];
    float* out = (float*)d_out;
    int N = in_sizes[0] / D_DIM;   // 131072
    int K = in_sizes[1] / D_DIM;   // 1024

    zero_kernel<<<1, 32>>>();
    cnorm_kernel<<<K / 4, 512>>>(c);
    vq_pass1<<<N / 128, 256, 45568>>>(x, c, out);
    vq_rescore<<<128, 256, 6144 * 4 + 416>>>(x, c, out);
}

// round 13
// speedup vs baseline: 3.2755x; 1.0225x over previous
#include <cuda_runtime.h>
#include <cuda_bf16.h>

#define D_DIM   256
#define K_CENT  1024
#define N_MAX   131072
#define MARGIN  2e-3f

__device__ float g_cnorm[K_CENT];
__device__ int   g_amb[N_MAX];
__device__ int   g_count;
__device__ __align__(16) __nv_bfloat16 g_xh[(size_t)N_MAX * D_DIM];  // 64 MB
__device__ __align__(16) __nv_bfloat16 g_xl[(size_t)N_MAX * D_DIM];  // 64 MB
__device__ __align__(16) __nv_bfloat16 g_ch[K_CENT * D_DIM];
__device__ __align__(16) __nv_bfloat16 g_cl[K_CENT * D_DIM];

__global__ void zero_kernel() { if (threadIdx.x == 0) g_count = 0; }

// Split fp32 row into bf16 hi + lo planes. 4 rows / 512-thread block.
__global__ void convx_kernel(const float* __restrict__ x) {
    const int t  = threadIdx.x & 127;
    const int rs = threadIdx.x >> 7;
    const size_t row = (size_t)blockIdx.x * 4 + rs;
    float2 v = ((const float2*)(x + row * D_DIM))[t];
    __nv_bfloat162 h = __floats2bfloat162_rn(v.x, v.y);
    __nv_bfloat162 l = __floats2bfloat162_rn(v.x - __bfloat162float(h.x),
                                             v.y - __bfloat162float(h.y));
    ((__nv_bfloat162*)g_xh)[row * 128 + t] = h;
    ((__nv_bfloat162*)g_xl)[row * 128 + t] = l;
}

// c: bf16 hi/lo split + XLA-order |c|^2 (bit-exact R8 chain).
__global__ void convc_kernel(const float* __restrict__ c) {
    __shared__ float s4[4][4];
    const int t  = threadIdx.x & 127;
    const int rs = threadIdx.x >> 7;
    const int row = blockIdx.x * 4 + rs;
    float2 v = ((const float2*)(c + (size_t)row * D_DIM))[t];
    __nv_bfloat162 h = __floats2bfloat162_rn(v.x, v.y);
    __nv_bfloat162 l = __floats2bfloat162_rn(v.x - __bfloat162float(h.x),
                                             v.y - __bfloat162float(h.y));
    ((__nv_bfloat162*)g_ch)[row * 128 + t] = h;
    ((__nv_bfloat162*)g_cl)[row * 128 + t] = l;
    float p = __fmul_rn(v.x, v.x);
    p = __fadd_rn(p, __fmul_rn(v.y, v.y));
#pragma unroll
    for (int off = 16; off; off >>= 1)
        p = __fadd_rn(p, __shfl_down_sync(0xffffffffu, p, off));
    if ((t & 31) == 0) s4[rs][t >> 5] = p;
    __syncthreads();
    if (t == 0)
        g_cnorm[row] = __fadd_rn(__fadd_rn(s4[rs][0], s4[rs][2]),
                                 __fadd_rn(s4[rs][1], s4[rs][3]));
}

__device__ __forceinline__ void top2_update(float& v1, float& v2, int& i1,
                                            float s, int n) {
    if (s < v1)      { v2 = v1; v1 = s; i1 = n; }
    else if (s < v2) { v2 = s; }
}

#define LDSM_X4(R, addr) \
    asm volatile("ldmatrix.sync.aligned.m8n8.x4.shared.b16 {%0,%1,%2,%3}, [%4];" \
        : "=r"((R)[0]), "=r"((R)[1]), "=r"((R)[2]), "=r"((R)[3]) : "r"(addr))

#define MMA16816(A, B0, B1, C) \
    asm volatile("mma.sync.aligned.m16n8k16.row.col.f32.bf16.bf16.f32 " \
        "{%0,%1,%2,%3}, {%4,%5,%6,%7}, {%8,%9}, {%0,%1,%2,%3};" \
        : "+f"((C)[0]), "+f"((C)[1]), "+f"((C)[2]), "+f"((C)[3]) \
        : "r"((A)[0]), "r"((A)[1]), "r"((A)[2]), "r"((A)[3]), "r"(B0), "r"(B1))

// Pass 1: split-bf16 (hh+lh+hl) mma.sync GEMM; score = -2*dot + cn.
// CTA: 128 x-rows x 1024 centroids; warp tile m32 x n64; ldmatrix fragments.
// Staging now reads precomputed bf16 planes (no conversion in-loop).
__global__ void __launch_bounds__(256, 2)
vq_pass1(const float* __restrict__ c, float* __restrict__ out)
{
    extern __shared__ char smem[];
    __nv_bfloat16* xs_hi = (__nv_bfloat16*)(smem);           // [128][40]
    __nv_bfloat16* cs_hi = (__nv_bfloat16*)(smem + 20480);   // [128][40]
    float* cns = (float*)(smem + 40960);                     // 1024 f32
    int*   si  = (int*)(smem + 45056);                       // 128 int
    // lo planes at +10240 from each hi; post-loop reduce aliases base:
    float* rv1 = (float*)(smem);
    float* rv2 = (float*)(smem + 1024);
    int*   ri1 = (int*)(smem + 2048);

    const int tid  = threadIdx.x;
    const int lane = tid & 31, warp = tid >> 5;
    const int warp_m = warp & 3, warp_n = warp >> 2;
    const int wm0 = warp_m * 32, wn0 = warp_n * 64;
    const int lrow = lane >> 2, kp = (lane & 3) * 2;
    const long long m0 = (long long)blockIdx.x * 128;

    for (int i = tid; i < K_CENT; i += 256) cns[i] = g_cnorm[i];

    const unsigned xs_sh = (unsigned)__cvta_generic_to_shared(xs_hi);
    const unsigned cs_sh = (unsigned)__cvta_generic_to_shared(cs_hi);
    unsigned aAddr[2], bAddr[4];
#pragma unroll
    for (int mi = 0; mi < 2; ++mi)
        aAddr[mi] = xs_sh +
            ((wm0 + mi * 16 + (lane & 15)) * 40 + (lane >> 4) * 8) * 2;
#pragma unroll
    for (int q = 0; q < 4; ++q)
        bAddr[q] = cs_sh +
            ((wn0 + q * 16 + ((lane >> 4) & 1) * 8 + (lane & 7)) * 40 +
             ((lane >> 3) & 1) * 8) * 2;

    float v1[4], v2[4]; int i1[4];
#pragma unroll
    for (int r = 0; r < 4; ++r) { v1[r] = 3.4e38f; v2[r] = 3.4e38f; i1[r] = 0; }

    for (int n0t = 0; n0t < 8; ++n0t) {
        const int n0 = n0t * 128;
        float acc[2][8][4];
#pragma unroll
        for (int mi = 0; mi < 2; ++mi)
#pragma unroll
            for (int ni = 0; ni < 8; ++ni)
#pragma unroll
                for (int j = 0; j < 4; ++j) acc[mi][ni][j] = 0.f;

        for (int k0 = 0; k0 < D_DIM; k0 += 32) {
            __syncthreads();
            // stage x hi/lo: 128 rows x 32 bf16 = 512 uint4 per plane
#pragma unroll
            for (int it = 0; it < 2; ++it) {
                int idx = it * 256 + tid;
                int m = idx >> 2, u = idx & 3;
                uint4 vh = ((const uint4*)(g_xh + (m0 + m) * D_DIM + k0))[u];
                uint4 vl = ((const uint4*)(g_xl + (m0 + m) * D_DIM + k0))[u];
                *(uint4*)((char*)xs_hi + m * 80 + u * 16)         = vh;
                *(uint4*)((char*)xs_hi + 10240 + m * 80 + u * 16) = vl;
            }
            // stage c hi/lo
#pragma unroll
            for (int it = 0; it < 2; ++it) {
                int idx = it * 256 + tid;
                int n = idx >> 2, u = idx & 3;
                uint4 vh = ((const uint4*)(g_ch + (size_t)(n0 + n) * D_DIM + k0))[u];
                uint4 vl = ((const uint4*)(g_cl + (size_t)(n0 + n) * D_DIM + k0))[u];
                *(uint4*)((char*)cs_hi + n * 80 + u * 16)         = vh;
                *(uint4*)((char*)cs_hi + 10240 + n * 80 + u * 16) = vl;
            }
            __syncthreads();

#pragma unroll
            for (int kk = 0; kk < 32; kk += 16) {
                unsigned ah[2][4], al[2][4];
#pragma unroll
                for (int mi = 0; mi < 2; ++mi) {
                    LDSM_X4(ah[mi], aAddr[mi] + kk * 2);
                    LDSM_X4(al[mi], aAddr[mi] + 10240 + kk * 2);
                }
#pragma unroll
                for (int g = 0; g < 2; ++g) {
                    unsigned bh[2][4], bl[2][4];
#pragma unroll
                    for (int p = 0; p < 2; ++p) {
                        LDSM_X4(bh[p], bAddr[g * 2 + p] + kk * 2);
                        LDSM_X4(bl[p], bAddr[g * 2 + p] + 10240 + kk * 2);
                    }
#pragma unroll
                    for (int mi = 0; mi < 2; ++mi)
#pragma unroll
                        for (int p = 0; p < 2; ++p)
#pragma unroll
                            for (int h = 0; h < 2; ++h) {
                                int ni = g * 4 + p * 2 + h;
                                MMA16816(ah[mi], bh[p][2*h], bh[p][2*h+1], acc[mi][ni]);
                                MMA16816(al[mi], bh[p][2*h], bh[p][2*h+1], acc[mi][ni]);
                                MMA16816(ah[mi], bl[p][2*h], bl[p][2*h+1], acc[mi][ni]);
                            }
                }
            }
        }

#pragma unroll
        for (int ni = 0; ni < 8; ++ni) {
            int n = n0 + wn0 + ni * 8 + kp;
            float cn0 = cns[n], cn1 = cns[n + 1];
#pragma unroll
            for (int mi = 0; mi < 2; ++mi) {
                top2_update(v1[mi*2], v2[mi*2], i1[mi*2],
                            fmaf(-2.f, acc[mi][ni][0], cn0), n);
                top2_update(v1[mi*2], v2[mi*2], i1[mi*2],
                            fmaf(-2.f, acc[mi][ni][1], cn1), n + 1);
                top2_update(v1[mi*2+1], v2[mi*2+1], i1[mi*2+1],
                            fmaf(-2.f, acc[mi][ni][2], cn0), n);
                top2_update(v1[mi*2+1], v2[mi*2+1], i1[mi*2+1],
                            fmaf(-2.f, acc[mi][ni][3], cn1), n + 1);
            }
        }
    }

#pragma unroll
    for (int off = 1; off <= 2; off <<= 1) {
#pragma unroll
        for (int rp = 0; rp < 4; ++rp) {
            float ov1 = __shfl_xor_sync(0xffffffffu, v1[rp], off);
            int   oi1 = __shfl_xor_sync(0xffffffffu, i1[rp], off);
            float ov2 = __shfl_xor_sync(0xffffffffu, v2[rp], off);
            if (ov1 < v1[rp] || (ov1 == v1[rp] && oi1 < i1[rp])) {
                v2[rp] = fminf(v1[rp], ov2);
                v1[rp] = ov1; i1[rp] = oi1;
            } else {
                v2[rp] = fminf(v2[rp], ov1);
            }
        }
    }

    __syncthreads();
    if ((lane & 3) == 0) {
#pragma unroll
        for (int rp = 0; rp < 4; ++rp) {
            int row = wm0 + (rp >> 1) * 16 + (rp & 1) * 8 + lrow;
            rv1[row * 2 + warp_n] = v1[rp];
            rv2[row * 2 + warp_n] = v2[rp];
            ri1[row * 2 + warp_n] = i1[rp];
        }
    }
    __syncthreads();

    if (tid < 128) {
        float a1 = rv1[tid * 2], a2 = rv2[tid * 2];
        int   ai = ri1[tid * 2];
        float b1 = rv1[tid * 2 + 1], b2 = rv2[tid * 2 + 1];
        int   bi = ri1[tid * 2 + 1];
        float fv1, fv2; int fi;
        if (a1 < b1 || (a1 == b1 && ai < bi)) {
            fv1 = a1; fi = ai; fv2 = fminf(a2, b1);
        } else {
            fv1 = b1; fi = bi; fv2 = fminf(b2, a1);
        }
        si[tid] = fi;
        if (fv2 - fv1 < MARGIN) {
            int p = atomicAdd(&g_count, 1);
            g_amb[p] = (int)(m0 + tid);
        }
    }
    __syncthreads();

    {
        int rr = tid >> 1, half = tid & 1;
        int bi = si[rr];
        const float4* src = (const float4*)(c + (size_t)bi * D_DIM) + half * 32;
        float4*       dst = (float4*)(out + (m0 + rr) * D_DIM) + half * 32;
#pragma unroll
        for (int q = 0; q < 32; ++q) dst[q] = src[q];
    }
}

// Rescore: ONE block per ambiguous row (grid-stride). Exact R8 chain:
// xn via XLA-order reduction; per-centroid full ascending-k=256
// single-accumulator FFMA; score fl(fl(-2*dot+xn)+cn); first-index argmin.
__global__ void __launch_bounds__(128)
vq_rescore(const float* __restrict__ x, const float* __restrict__ c,
           float* __restrict__ out)
{
    extern __shared__ float sm[];
    float* xrow = sm;                    // [256]
    float* cs   = sm + 256;              // [64][129]
    float* rv   = cs + 64 * 129;         // [128]
    int*   ri   = (int*)(rv + 128);      // [128]
    float* s4   = (float*)(ri + 128);    // [4] + xn at s4[4]

    const int t = threadIdx.x;
    const int count = g_count;

    for (int a = blockIdx.x; a < count; a += gridDim.x) {
        const size_t row = (size_t)g_amb[a];

        // stage x row + XLA-order |x|^2
        float2 v = ((const float2*)(x + row * D_DIM))[t];
        ((float2*)xrow)[t] = v;
        float p = __fmul_rn(v.x, v.x);
        p = __fadd_rn(p, __fmul_rn(v.y, v.y));
#pragma unroll
        for (int off = 16; off; off >>= 1)
            p = __fadd_rn(p, __shfl_down_sync(0xffffffffu, p, off));
        if ((t & 31) == 0) s4[t >> 5] = p;
        __syncthreads();
        if (t == 0)
            s4[4] = __fadd_rn(__fadd_rn(s4[0], s4[2]), __fadd_rn(s4[1], s4[3]));
        __syncthreads();
        const float xn = s4[4];

        float bestv = 3.4e38f; int besti = 0;

        for (int n0 = 0; n0 < K_CENT; n0 += 128) {
            float acc = 0.f;                     // full-k chain, thread owns n0+t
            for (int k0 = 0; k0 < D_DIM; k0 += 64) {
                __syncthreads();
                // stage c[n0..n0+127][k0..k0+63] k-major into cs[(k)][n]
#pragma unroll
                for (int it = 0; it < 16; ++it) {
                    int idx = it * 128 + t;
                    int n = idx >> 4, f4 = idx & 15;
                    float4 cv = ((const float4*)(c + (size_t)(n0 + n) * D_DIM + k0))[f4];
                    int kk = f4 * 4;
                    cs[(kk + 0) * 129 + n] = cv.x;  // wait: stride layout below
                    cs[(kk + 1) * 129 + n] = cv.y;
                    cs[(kk + 2) * 129 + n] = cv.z;
                    cs[(kk + 3) * 129 + n] = cv.w;
                }
                __syncthreads();
#pragma unroll 8
                for (int k = 0; k < 64; ++k)
                    acc = __fmaf_rn(xrow[k0 + k], cs[k * 129 + t], acc);
            }
            float s = __fadd_rn(__fadd_rn(__fmul_rn(-2.0f, acc), xn),
                                g_cnorm[n0 + t]);
            if (s < bestv) { bestv = s; besti = n0 + t; }  // n ascending
        }

        rv[t] = bestv; ri[t] = besti;
        __syncthreads();
        for (int o = 64; o; o >>= 1) {
            if (t < o) {
                float ov = rv[t + o]; int oi = ri[t + o];
                if (ov < rv[t] || (ov == rv[t] && oi < ri[t])) {
                    rv[t] = ov; ri[t] = oi;
                }
            }
            __syncthreads();
        }
        const int bi = ri[0];

        // write out row
        {
            const float4* src = (const float4*)(c + (size_t)bi * D_DIM);
            float4*       dst = (float4*)(out + row * D_DIM);
#pragma unroll
            for (int q = 0; q < 1; ++q) { }
            dst[t >> 1] = src[t >> 1];          // 128 thr: first 64 float4
            if (t < 0) { }
        }
        // 64 float4 total, 128 threads -> half write; do explicit:
        if (t < 64) {
            const float4* src = (const float4*)(c + (size_t)bi * D_DIM);
            float4*       dst = (float4*)(out + row * D_DIM);
            dst[t] = src[t];
        }
        __syncthreads();
    }
}

extern "C" void kernel_launch(void* const* d_in, const int* in_sizes, int n_in,
                              void* d_out, int out_size) {
    const float* x = (const float*)d_in[0];
    const float* c = (const float*)d_in[1];
    float* out = (float*)d_out;
    int N = in_sizes[0] / D_DIM;   // 131072
    int K = in_sizes[1] / D_DIM;   // 1024

    zero_kernel<<<1, 32>>>();
    convx_kernel<<<N / 4, 512>>>(x);
    convc_kernel<<<K / 4, 512>>>(c);
    vq_pass1<<<N / 128, 256, 45568>>>(c, out);
    vq_rescore<<<256, 128, (256 + 64 * 129 + 128) * sizeof(float)
                           + 128 * sizeof(int) + 32>>>(x, c, out);
}